// round 14
// baseline (speedup 1.0000x reference)
#include <cuda_runtime.h>
#include <cuda_fp16.h>
#include <cstdint>
#include <math.h>

#define BB 4
#define SS 4096
#define DD 256
#define ROWS (BB*SS)

// Scratch (device globals — no allocation in kernel_launch)
__device__ __half g_w4[4*DD*DD];          // Wq|Wk|Wv|Wl in fp16
__device__ __half g_qh[ROWS*DD];
__device__ __half g_kh[ROWS*DD];
__device__ __half g_vh[ROWS*DD];
__device__ __half g_hh[ROWS*DD];          // LN1 output (fp16)

// ---------------------------------------------------------------------------
// helpers
// ---------------------------------------------------------------------------
__device__ __forceinline__ uint32_t smem_u32(const void* p) {
    return (uint32_t)__cvta_generic_to_shared(p);
}
__device__ __forceinline__ void ldsm4(uint32_t& r0, uint32_t& r1, uint32_t& r2, uint32_t& r3, uint32_t a) {
    asm volatile("ldmatrix.sync.aligned.m8n8.x4.shared.b16 {%0,%1,%2,%3},[%4];"
                 : "=r"(r0), "=r"(r1), "=r"(r2), "=r"(r3) : "r"(a));
}
__device__ __forceinline__ void ldsm4t(uint32_t& r0, uint32_t& r1, uint32_t& r2, uint32_t& r3, uint32_t a) {
    asm volatile("ldmatrix.sync.aligned.m8n8.x4.trans.shared.b16 {%0,%1,%2,%3},[%4];"
                 : "=r"(r0), "=r"(r1), "=r"(r2), "=r"(r3) : "r"(a));
}
__device__ __forceinline__ void mma16816(float* c, uint32_t a0, uint32_t a1, uint32_t a2, uint32_t a3,
                                         uint32_t b0, uint32_t b1) {
    asm volatile("mma.sync.aligned.m16n8k16.row.col.f32.f16.f16.f32 "
                 "{%0,%1,%2,%3},{%4,%5,%6,%7},{%8,%9},{%0,%1,%2,%3};"
                 : "+f"(c[0]), "+f"(c[1]), "+f"(c[2]), "+f"(c[3])
                 : "r"(a0), "r"(a1), "r"(a2), "r"(a3), "r"(b0), "r"(b1));
}
__device__ __forceinline__ uint32_t packh2(float lo, float hi) {
    __half2 h = __floats2half2_rn(lo, hi);
    return *reinterpret_cast<uint32_t*>(&h);
}
__device__ __forceinline__ void cpa16(uint32_t dst, const void* src) {
    asm volatile("cp.async.cg.shared.global [%0], [%1], 16;" :: "r"(dst), "l"(src));
}
__device__ __forceinline__ void cpa_commit() { asm volatile("cp.async.commit_group;"); }
template<int N>
__device__ __forceinline__ void cpa_wait() { asm volatile("cp.async.wait_group %0;" :: "n"(N)); }

// ---------------------------------------------------------------------------
// fp32 -> fp16 converter for the 4 weight matrices (tiny: 128 blocks)
// ---------------------------------------------------------------------------
__global__ __launch_bounds__(256) void cvt_w(const float* __restrict__ w0,
                                             const float* __restrict__ w1,
                                             const float* __restrict__ w2,
                                             const float* __restrict__ w3,
                                             __half* __restrict__ dw) {
    int y = blockIdx.x >> 5;
    const float* s = (y == 0) ? w0 : (y == 1) ? w1 : (y == 2) ? w2 : w3;
    int i = ((blockIdx.x & 31) * 256 + threadIdx.x) * 8;
    float4 a = *(const float4*)(s + i);
    float4 c = *(const float4*)(s + i + 4);
    uint4 u;
    u.x = packh2(a.x, a.y); u.y = packh2(a.z, a.w);
    u.z = packh2(c.x, c.y); u.w = packh2(c.z, c.w);
    *(uint4*)(dw + y * DD * DD + i) = u;
}

// ---------------------------------------------------------------------------
// QKV GEMM, persistent over z: fp32 x-tile (128x256) loaded ONCE, converted
// to fp16 during the smem store, reused for all three weight streams
// (W chunks cp.async double-buffered). grid (2, 128); warp = m32 x n64.
// ---------------------------------------------------------------------------
#define GLDH 72
#define QLDH 264
#define QA_B   (128 * QLDH * 2)        // full A tile bytes (67584)
#define QW_STG (128 * GLDH * 2)        // W chunk stage bytes (18432)
#define QKV_SMEM (QA_B + 2 * QW_STG)

__global__ __launch_bounds__(256) void qkv_k(const float* __restrict__ X,
                                             const __half* Wq, const __half* Wk, const __half* Wv,
                                             const float* bq, const float* bk, const float* bv,
                                             __half* Cq, __half* Ck, __half* Cvv) {
    extern __shared__ __align__(16) char smraw[];
    const uint32_t sA = smem_u32(smraw);
    const uint32_t sW = sA + QA_B;
    __half* sAh = (__half*)smraw;
    const int tid  = threadIdx.x;
    const int warp = tid >> 5, lane = tid & 31;
    const int wm = warp & 3, wn = warp >> 2;
    const int m0 = blockIdx.y * 128;
    const int n0 = blockIdx.x * 128;

    // ---- load full fp32 x tile 128x256, convert to fp16 during STS ----
    for (int i = tid; i < 4096; i += 256) {
        int r = i >> 5, c8 = (i & 31) * 8;
        const float* xp = X + (size_t)(m0 + r) * 256 + c8;
        float4 f0 = *(const float4*)xp, f1 = *(const float4*)(xp + 4);
        uint4 u;
        u.x = packh2(f0.x, f0.y); u.y = packh2(f0.z, f0.w);
        u.z = packh2(f1.x, f1.y); u.w = packh2(f1.z, f1.w);
        *(uint4*)(sAh + r * QLDH + c8) = u;
    }

    const uint32_t aBase = sA + ((wm * 32 + (lane & 15)) * QLDH + (lane >> 4) * 8) * 2;
    const uint32_t wBase = sW + ((wn * 64 + (lane & 7) + ((lane >> 4) & 1) * 8) * GLDH + ((lane >> 3) & 1) * 8) * 2;
    const int g = lane >> 2, qd = lane & 3;

    #pragma unroll 1
    for (int z = 0; z < 3; z++) {
        const __half* W   = (z == 0) ? Wq : (z == 1) ? Wk : Wv;
        const float* bias = (z == 0) ? bq : (z == 1) ? bk : bv;
        __half* Cv        = (z == 0) ? Cq : (z == 1) ? Ck : Cvv;
        const float scale = (z == 0) ? 0.0625f : 1.0f;

        // prologue: W chunk 0 -> stage 0
        for (int i = tid; i < 1024; i += 256) {
            int r = i >> 3, c8 = (i & 7) * 8;
            cpa16(sW + (r * GLDH + c8) * 2, W + (size_t)(n0 + r) * 256 + c8);
        }
        cpa_commit();

        float acc[2][8][4] = {};
        for (int kci = 0; kci < 4; kci++) {
            if (kci < 3) {
                const uint32_t so = ((kci + 1) & 1) * QW_STG;
                const int kc = (kci + 1) * 64;
                for (int i = tid; i < 1024; i += 256) {
                    int r = i >> 3, c8 = (i & 7) * 8;
                    cpa16(sW + so + (r * GLDH + c8) * 2, W + (size_t)(n0 + r) * 256 + kc + c8);
                }
            }
            cpa_commit();
            cpa_wait<1>();
            __syncthreads();

            const uint32_t wAddr = wBase + (kci & 1) * QW_STG;
            const uint32_t aAddr = aBase + kci * 64 * 2;
            #pragma unroll
            for (int kk = 0; kk < 4; kk++) {
                uint32_t a[2][4];
                ldsm4(a[0][0], a[0][1], a[0][2], a[0][3], aAddr + kk * 32);
                ldsm4(a[1][0], a[1][1], a[1][2], a[1][3], aAddr + 16 * QLDH * 2 + kk * 32);
                #pragma unroll
                for (int j = 0; j < 4; j++) {
                    uint32_t b0r, b1r, b2r, b3r;
                    ldsm4(b0r, b1r, b2r, b3r, wAddr + j * 16 * GLDH * 2 + kk * 32);
                    mma16816(acc[0][2 * j],     a[0][0], a[0][1], a[0][2], a[0][3], b0r, b1r);
                    mma16816(acc[0][2 * j + 1], a[0][0], a[0][1], a[0][2], a[0][3], b2r, b3r);
                    mma16816(acc[1][2 * j],     a[1][0], a[1][1], a[1][2], a[1][3], b0r, b1r);
                    mma16816(acc[1][2 * j + 1], a[1][0], a[1][1], a[1][2], a[1][3], b2r, b3r);
                }
            }
            __syncthreads();
        }

        #pragma unroll
        for (int s = 0; s < 2; s++) {
            int row0 = m0 + wm * 32 + s * 16 + g;
            #pragma unroll
            for (int j = 0; j < 8; j++) {
                int col = n0 + wn * 64 + j * 8 + qd * 2;
                float bb0 = bias[col], bb1 = bias[col + 1];
                float v00 = acc[s][j][0] + bb0, v01 = acc[s][j][1] + bb1;
                float v10 = acc[s][j][2] + bb0, v11 = acc[s][j][3] + bb1;
                *(uint32_t*)(Cv + (size_t)row0 * 256 + col)       = packh2(v00 * scale, v01 * scale);
                *(uint32_t*)(Cv + (size_t)(row0 + 8) * 256 + col) = packh2(v10 * scale, v11 * scale);
            }
        }
    }
}

// ---------------------------------------------------------------------------
// Flash attention (round-12 proven, UNCHANGED: fp16 mma + online softmax +
// cp.async double-buffered K/V + fused LN1 epilogue -> ghh fp16)
// ---------------------------------------------------------------------------
#define LDH 264
#define BRQ 128
#define QTILEH (BRQ * LDH)
#define TILEH (64 * LDH)
#define STGH  (2 * TILEH)
#define FLASH_SMEM ((QTILEH + 2 * STGH) * (int)sizeof(__half))
#define L2E 1.44269504f

__global__ __launch_bounds__(256, 1) void flash_h(const __half* __restrict__ Q,
                                                  const __half* __restrict__ K,
                                                  const __half* __restrict__ V,
                                                  const float* __restrict__ X,
                                                  const float* __restrict__ g1,
                                                  const float* __restrict__ be1,
                                                  __half* __restrict__ H) {
    extern __shared__ __half sm[];
    __half* sQ  = sm;
    __half* sK0 = sm + QTILEH;
    __half* sV0 = sK0 + TILEH;

    const int b  = blockIdx.y;
    const int q0 = blockIdx.x * BRQ;
    const int tid = threadIdx.x;
    const int warp = tid >> 5;
    const int lane = tid & 31;
    const int g  = lane >> 2;
    const int qd = lane & 3;

    const __half* Qb = Q + ((size_t)b * SS + q0) * DD;
    const __half* Kb = K + (size_t)b * SS * DD;
    const __half* Vb = V + (size_t)b * SS * DD;

    for (int c = tid; c < 4096; c += 256) {
        int r = c >> 5, co = (c & 31) * 8;
        cpa16(smem_u32(sQ + r * LDH + co), Qb + (size_t)r * 256 + co);
    }
    {
        const uint32_t kDst = smem_u32(sK0);
        for (int c = tid; c < 2048; c += 256) {
            int r = c >> 5, co = (c & 31) * 8;
            cpa16(kDst + (r * LDH + co) * 2,         Kb + (size_t)r * 256 + co);
            cpa16(kDst + (TILEH + r * LDH + co) * 2, Vb + (size_t)r * 256 + co);
        }
        cpa_commit();
    }

    float o[32][4];
    #pragma unroll
    for (int t = 0; t < 32; t++) { o[t][0] = 0; o[t][1] = 0; o[t][2] = 0; o[t][3] = 0; }
    float m0 = -1e30f, m1 = -1e30f, l0 = 0.0f, l1 = 0.0f;

    const uint32_t aBase  = smem_u32(sQ + (warp * 16 + (lane & 15)) * LDH + (lane >> 4) * 8);
    const uint32_t kBase0 = smem_u32(sK0 + ((lane & 7) + ((lane >> 4) & 1) * 8) * LDH + ((lane >> 3) & 1) * 8);
    const uint32_t vBase0 = smem_u32(sV0 + (lane & 15) * LDH + (lane >> 4) * 8);
    const uint32_t kDst0  = smem_u32(sK0);

    for (int ti = 0; ti < SS / 64; ti++) {
        if (ti + 1 < SS / 64) {
            const uint32_t kDst = kDst0 + ((ti + 1) & 1) * STGH * 2;
            const __half* Kn = Kb + (size_t)(ti + 1) * 64 * 256;
            const __half* Vn = Vb + (size_t)(ti + 1) * 64 * 256;
            for (int c = tid; c < 2048; c += 256) {
                int r = c >> 5, co = (c & 31) * 8;
                cpa16(kDst + (r * LDH + co) * 2,         Kn + (size_t)r * 256 + co);
                cpa16(kDst + (TILEH + r * LDH + co) * 2, Vn + (size_t)r * 256 + co);
            }
        }
        cpa_commit();
        cpa_wait<1>();
        __syncthreads();

        const uint32_t kBase = kBase0 + (ti & 1) * STGH * 2;
        const uint32_t vBase = vBase0 + (ti & 1) * STGH * 2;

        float s[8][4];
        #pragma unroll
        for (int j = 0; j < 8; j++) { s[j][0] = 0; s[j][1] = 0; s[j][2] = 0; s[j][3] = 0; }

        #pragma unroll
        for (int kk = 0; kk < 16; kk++) {
            uint32_t a0, a1, a2, a3;
            ldsm4(a0, a1, a2, a3, aBase + kk * 32);
            #pragma unroll
            for (int jj = 0; jj < 4; jj++) {
                uint32_t k0, k1, k2, k3;
                ldsm4(k0, k1, k2, k3, kBase + jj * 16 * LDH * 2 + kk * 32);
                mma16816(s[2 * jj],     a0, a1, a2, a3, k0, k1);
                mma16816(s[2 * jj + 1], a0, a1, a2, a3, k2, k3);
            }
        }

        float rmax0 = -1e30f, rmax1 = -1e30f;
        #pragma unroll
        for (int j = 0; j < 8; j++) {
            rmax0 = fmaxf(rmax0, fmaxf(s[j][0], s[j][1]));
            rmax1 = fmaxf(rmax1, fmaxf(s[j][2], s[j][3]));
        }
        rmax0 = fmaxf(rmax0, __shfl_xor_sync(0xffffffffu, rmax0, 1));
        rmax0 = fmaxf(rmax0, __shfl_xor_sync(0xffffffffu, rmax0, 2));
        rmax1 = fmaxf(rmax1, __shfl_xor_sync(0xffffffffu, rmax1, 1));
        rmax1 = fmaxf(rmax1, __shfl_xor_sync(0xffffffffu, rmax1, 2));

        float mn0 = fmaxf(m0, rmax0), mn1 = fmaxf(m1, rmax1);
        float corr0 = exp2f((m0 - mn0) * L2E);
        float corr1 = exp2f((m1 - mn1) * L2E);
        m0 = mn0; m1 = mn1;

        uint32_t pl[8], ph[8];
        float rs0 = 0.0f, rs1 = 0.0f;
        #pragma unroll
        for (int j = 0; j < 8; j++) {
            float p0 = exp2f((s[j][0] - mn0) * L2E);
            float p1 = exp2f((s[j][1] - mn0) * L2E);
            float p2 = exp2f((s[j][2] - mn1) * L2E);
            float p3 = exp2f((s[j][3] - mn1) * L2E);
            rs0 += p0 + p1; rs1 += p2 + p3;
            pl[j] = packh2(p0, p1);
            ph[j] = packh2(p2, p3);
        }
        rs0 += __shfl_xor_sync(0xffffffffu, rs0, 1);
        rs0 += __shfl_xor_sync(0xffffffffu, rs0, 2);
        rs1 += __shfl_xor_sync(0xffffffffu, rs1, 1);
        rs1 += __shfl_xor_sync(0xffffffffu, rs1, 2);
        l0 = l0 * corr0 + rs0;
        l1 = l1 * corr1 + rs1;

        #pragma unroll
        for (int t = 0; t < 32; t++) {
            o[t][0] *= corr0; o[t][1] *= corr0;
            o[t][2] *= corr1; o[t][3] *= corr1;
        }

        #pragma unroll
        for (int kk2 = 0; kk2 < 4; kk2++) {
            uint32_t a0 = pl[2 * kk2], a1 = ph[2 * kk2];
            uint32_t a2 = pl[2 * kk2 + 1], a3 = ph[2 * kk2 + 1];
            uint32_t vrow = vBase + kk2 * 16 * LDH * 2;
            #pragma unroll
            for (int nj = 0; nj < 16; nj++) {
                uint32_t v0, v1, v2, v3;
                ldsm4t(v0, v1, v2, v3, vrow + nj * 32);
                mma16816(o[2 * nj],     a0, a1, a2, a3, v0, v1);
                mma16816(o[2 * nj + 1], a0, a1, a2, a3, v2, v3);
            }
        }
        __syncthreads();
    }

    // ---- fused LN1 epilogue ----
    float inv0 = 1.0f / l0, inv1 = 1.0f / l1;
    const size_t grow0 = (size_t)(b * SS + q0 + warp * 16 + g);
    const float* x0 = X + grow0 * 256;
    const float* x1 = x0 + 8 * 256;

    float s0 = 0.0f, ss0 = 0.0f, s1 = 0.0f, ss1 = 0.0f;
    #pragma unroll
    for (int j = 0; j < 32; j++) {
        int col = j * 8 + qd * 2;
        float2 xa = *(const float2*)(x0 + col);
        float2 xb = *(const float2*)(x1 + col);
        float va0 = xa.x + o[j][0] * inv0, va1 = xa.y + o[j][1] * inv0;
        float vb0 = xb.x + o[j][2] * inv1, vb1 = xb.y + o[j][3] * inv1;
        o[j][0] = va0; o[j][1] = va1; o[j][2] = vb0; o[j][3] = vb1;
        s0 += va0 + va1; ss0 += va0 * va0 + va1 * va1;
        s1 += vb0 + vb1; ss1 += vb0 * vb0 + vb1 * vb1;
    }
    s0  += __shfl_xor_sync(0xffffffffu, s0, 1);  s0  += __shfl_xor_sync(0xffffffffu, s0, 2);
    ss0 += __shfl_xor_sync(0xffffffffu, ss0, 1); ss0 += __shfl_xor_sync(0xffffffffu, ss0, 2);
    s1  += __shfl_xor_sync(0xffffffffu, s1, 1);  s1  += __shfl_xor_sync(0xffffffffu, s1, 2);
    ss1 += __shfl_xor_sync(0xffffffffu, ss1, 1); ss1 += __shfl_xor_sync(0xffffffffu, ss1, 2);
    float mu0 = s0 * (1.0f / 256.0f), mu1 = s1 * (1.0f / 256.0f);
    float rstd0 = rsqrtf(fmaxf(ss0 * (1.0f / 256.0f) - mu0 * mu0, 0.0f) + 1e-5f);
    float rstd1 = rsqrtf(fmaxf(ss1 * (1.0f / 256.0f) - mu1 * mu1, 0.0f) + 1e-5f);

    __half* h0 = H + grow0 * 256;
    __half* h1 = h0 + 8 * 256;
    #pragma unroll
    for (int j = 0; j < 32; j++) {
        int col = j * 8 + qd * 2;
        float2 gg = *(const float2*)(g1 + col);
        float2 bb = *(const float2*)(be1 + col);
        *(uint32_t*)(h0 + col) = packh2((o[j][0] - mu0) * rstd0 * gg.x + bb.x,
                                        (o[j][1] - mu0) * rstd0 * gg.y + bb.y);
        *(uint32_t*)(h1 + col) = packh2((o[j][2] - mu1) * rstd1 * gg.x + bb.x,
                                        (o[j][3] - mu1) * rstd1 * gg.y + bb.y);
    }
}

// ---------------------------------------------------------------------------
// Fused MLP + LN2, persistent over 2 row-tiles. LN2 stats pass folds x into
// acc so the write pass never reloads x.
// ---------------------------------------------------------------------------
#define MLDH 264
#define MWB (256 * MLDH * 2)
#define MHB (64 * MLDH * 2)
#define MLP_SMEM (MWB + 2 * MHB + 1024)

__global__ __launch_bounds__(256, 1) void mlp_k(const __half* __restrict__ H,
                                                const __half* __restrict__ Wl,
                                                const float* __restrict__ bl,
                                                const float* __restrict__ X,
                                                const float* __restrict__ g2,
                                                const float* __restrict__ be2,
                                                float* __restrict__ out) {
    extern __shared__ __align__(16) char smraw[];
    const uint32_t sW = smem_u32(smraw);
    const uint32_t sH = sW + MWB;
    const uint32_t sT = sH + MHB;
    float2* pLN = (float2*)(smraw + MWB + 2 * MHB);

    const int tid  = threadIdx.x;
    const int warp = tid >> 5, lane = tid & 31;
    const int wm = warp & 3, wn = warp >> 2;
    const int g  = lane >> 2, qd = lane & 3;

    for (int i = tid; i < 8192; i += 256) {
        int r = i >> 5, c8 = (i & 31) * 8;
        cpa16(sW + (r * MLDH + c8) * 2, Wl + (size_t)r * 256 + c8);
    }
    cpa_commit();

    const uint32_t aH = sH + (((wm * 16 + (lane & 15)) * MLDH + (lane >> 4) * 8)) * 2;
    const uint32_t aT = sT + (((wm * 16 + (lane & 15)) * MLDH + (lane >> 4) * 8)) * 2;
    const uint32_t wA = sW + (((wn * 128 + (lane & 7) + ((lane >> 4) & 1) * 8) * MLDH + ((lane >> 3) & 1) * 8)) * 2;
    const int row0 = wm * 16 + g;

    for (int it = 0; it < 2; it++) {
        const int m0 = (blockIdx.x * 2 + it) * 64;

        for (int i = tid; i < 2048; i += 256) {
            int r = i >> 5, c8 = (i & 31) * 8;
            cpa16(sH + (r * MLDH + c8) * 2, H + (size_t)(m0 + r) * 256 + c8);
        }
        cpa_commit();
        cpa_wait<0>();
        __syncthreads();

        // ---- GEMM1: t = relu(h @ Wl^T + bl) ----
        {
            float acc[16][4] = {};
            #pragma unroll
            for (int kk = 0; kk < 16; kk++) {
                uint32_t a0, a1, a2, a3;
                ldsm4(a0, a1, a2, a3, aH + kk * 32);
                #pragma unroll
                for (int jj = 0; jj < 8; jj++) {
                    uint32_t b0, b1, b2, b3;
                    ldsm4(b0, b1, b2, b3, wA + jj * 16 * MLDH * 2 + kk * 32);
                    mma16816(acc[2 * jj],     a0, a1, a2, a3, b0, b1);
                    mma16816(acc[2 * jj + 1], a0, a1, a2, a3, b2, b3);
                }
            }
            #pragma unroll
            for (int f = 0; f < 16; f++) {
                int col = wn * 128 + f * 8 + qd * 2;
                float b0 = bl[col], b1 = bl[col + 1];
                float v00 = fmaxf(acc[f][0] + b0, 0.0f), v01 = fmaxf(acc[f][1] + b1, 0.0f);
                float v10 = fmaxf(acc[f][2] + b0, 0.0f), v11 = fmaxf(acc[f][3] + b1, 0.0f);
                asm volatile("st.shared.b32 [%0], %1;" :: "r"(sT + (row0 * MLDH + col) * 2), "r"(packh2(v00, v01)) : "memory");
                asm volatile("st.shared.b32 [%0], %1;" :: "r"(sT + ((row0 + 8) * MLDH + col) * 2), "r"(packh2(v10, v11)) : "memory");
            }
        }
        __syncthreads();

        // ---- GEMM2: t2 = t @ Wl^T + bl ----
        float acc[16][4] = {};
        #pragma unroll
        for (int kk = 0; kk < 16; kk++) {
            uint32_t a0, a1, a2, a3;
            ldsm4(a0, a1, a2, a3, aT + kk * 32);
            #pragma unroll
            for (int jj = 0; jj < 8; jj++) {
                uint32_t b0, b1, b2, b3;
                ldsm4(b0, b1, b2, b3, wA + jj * 16 * MLDH * 2 + kk * 32);
                mma16816(acc[2 * jj],     a0, a1, a2, a3, b0, b1);
                mma16816(acc[2 * jj + 1], a0, a1, a2, a3, b2, b3);
            }
        }
        #pragma unroll
        for (int f = 0; f < 16; f++) {
            int col = wn * 128 + f * 8 + qd * 2;
            acc[f][0] += bl[col]; acc[f][1] += bl[col + 1];
            acc[f][2] += bl[col]; acc[f][3] += bl[col + 1];
        }

        // ---- fused LN2 (x folded into acc; write pass reloads nothing) ----
        const float* x0 = X + (size_t)(m0 + row0) * 256;
        const float* x1 = x0 + 8 * 256;

        float s0 = 0.0f, ss0 = 0.0f, s1 = 0.0f, ss1 = 0.0f;
        #pragma unroll
        for (int f = 0; f < 16; f++) {
            int col = wn * 128 + f * 8 + qd * 2;
            float2 xa = *(const float2*)(x0 + col);
            float2 xb = *(const float2*)(x1 + col);
            float va0 = xa.x + acc[f][0], va1 = xa.y + acc[f][1];
            float vb0 = xb.x + acc[f][2], vb1 = xb.y + acc[f][3];
            acc[f][0] = va0; acc[f][1] = va1; acc[f][2] = vb0; acc[f][3] = vb1;
            s0 += va0 + va1; ss0 += va0 * va0 + va1 * va1;
            s1 += vb0 + vb1; ss1 += vb0 * vb0 + vb1 * vb1;
        }
        s0  += __shfl_xor_sync(0xffffffffu, s0, 1);  s0  += __shfl_xor_sync(0xffffffffu, s0, 2);
        ss0 += __shfl_xor_sync(0xffffffffu, ss0, 1); ss0 += __shfl_xor_sync(0xffffffffu, ss0, 2);
        s1  += __shfl_xor_sync(0xffffffffu, s1, 1);  s1  += __shfl_xor_sync(0xffffffffu, s1, 2);
        ss1 += __shfl_xor_sync(0xffffffffu, ss1, 1); ss1 += __shfl_xor_sync(0xffffffffu, ss1, 2);
        if (qd == 0) {
            pLN[row0 * 2 + wn]       = make_float2(s0, ss0);
            pLN[(row0 + 8) * 2 + wn] = make_float2(s1, ss1);
        }
        __syncthreads();
        float2 pa0 = pLN[row0 * 2],       pa1 = pLN[row0 * 2 + 1];
        float2 pb0 = pLN[(row0 + 8) * 2], pb1 = pLN[(row0 + 8) * 2 + 1];
        float mu0 = (pa0.x + pa1.x) * (1.0f / 256.0f);
        float mu1 = (pb0.x + pb1.x) * (1.0f / 256.0f);
        float rstd0 = rsqrtf(fmaxf((pa0.y + pa1.y) * (1.0f / 256.0f) - mu0 * mu0, 0.0f) + 1e-5f);
        float rstd1 = rsqrtf(fmaxf((pb0.y + pb1.y) * (1.0f / 256.0f) - mu1 * mu1, 0.0f) + 1e-5f);

        float* o0 = out + (size_t)(m0 + row0) * 256;
        float* o1 = o0 + 8 * 256;
        #pragma unroll
        for (int f = 0; f < 16; f++) {
            int col = wn * 128 + f * 8 + qd * 2;
            float2 gg = *(const float2*)(g2 + col);
            float2 bb = *(const float2*)(be2 + col);
            float2 w0, w1;
            w0.x = (acc[f][0] - mu0) * rstd0 * gg.x + bb.x;
            w0.y = (acc[f][1] - mu0) * rstd0 * gg.y + bb.y;
            w1.x = (acc[f][2] - mu1) * rstd1 * gg.x + bb.x;
            w1.y = (acc[f][3] - mu1) * rstd1 * gg.y + bb.y;
            *(float2*)(o0 + col) = w0;
            *(float2*)(o1 + col) = w1;
        }
        __syncthreads();
    }
}

// ---------------------------------------------------------------------------
extern "C" void kernel_launch(void* const* d_in, const int* in_sizes, int n_in,
                              void* d_out, int out_size) {
    (void)in_sizes; (void)n_in; (void)out_size;
    const float* x  = (const float*)d_in[0];
    const float* Wq = (const float*)d_in[1];
    const float* bq = (const float*)d_in[2];
    const float* Wk = (const float*)d_in[3];
    const float* bk = (const float*)d_in[4];
    const float* Wv = (const float*)d_in[5];
    const float* bv = (const float*)d_in[6];
    const float* Wl = (const float*)d_in[7];
    const float* bl = (const float*)d_in[8];
    const float* g1 = (const float*)d_in[9];
    const float* be1= (const float*)d_in[10];
    const float* g2 = (const float*)d_in[11];
    const float* be2= (const float*)d_in[12];
    float* out = (float*)d_out;

    __half *gw, *gq, *gk, *gv, *ghh;
    cudaGetSymbolAddress((void**)&gw,  g_w4);
    cudaGetSymbolAddress((void**)&gq,  g_qh);
    cudaGetSymbolAddress((void**)&gk,  g_kh);
    cudaGetSymbolAddress((void**)&gv,  g_vh);
    cudaGetSymbolAddress((void**)&ghh, g_hh);

    cudaFuncSetAttribute(flash_h, cudaFuncAttributeMaxDynamicSharedMemorySize, FLASH_SMEM);
    cudaFuncSetAttribute(qkv_k,   cudaFuncAttributeMaxDynamicSharedMemorySize, QKV_SMEM);
    cudaFuncSetAttribute(mlp_k,   cudaFuncAttributeMaxDynamicSharedMemorySize, MLP_SMEM);

    const __half* wq = gw;
    const __half* wk = gw + DD * DD;
    const __half* wv = gw + 2 * DD * DD;
    const __half* wl = gw + 3 * DD * DD;

    // fp32 -> fp16 staging (weights only; x converts inside qkv_k)
    cvt_w<<<128, 256>>>(Wq, Wk, Wv, Wl, gw);

    // QKV projection, persistent over q/k/v with resident x-tile
    qkv_k<<<dim3(2, 128), 256, QKV_SMEM>>>(x, wq, wk, wv, bq, bk, bv, gq, gk, gv);

    // flash attention + fused LN1 -> ghh (fp16)
    flash_h<<<dim3(SS / BRQ, BB), 256, FLASH_SMEM>>>(gq, gk, gv, x, g1, be1, ghh);

    // fused MLP + LN2 (persistent 2 tiles)
    mlp_k<<<ROWS / 128, 256, MLP_SMEM>>>(ghh, wl, bl, x, g2, be2, out);
}

// round 15
// speedup vs baseline: 1.0086x; 1.0086x over previous
#include <cuda_runtime.h>
#include <cuda_fp16.h>
#include <cstdint>
#include <math.h>

#define BB 4
#define SS 4096
#define DD 256
#define ROWS (BB*SS)

// Scratch (device globals — no allocation in kernel_launch)
__device__ __half g_w4[4*DD*DD];          // Wq|Wk|Wv|Wl in fp16
__device__ __half g_qh[ROWS*DD];
__device__ __half g_kh[ROWS*DD];
__device__ __half g_vh[ROWS*DD];
__device__ __half g_hh[ROWS*DD];          // LN1 output (fp16)

// ---------------------------------------------------------------------------
// helpers
// ---------------------------------------------------------------------------
__device__ __forceinline__ uint32_t smem_u32(const void* p) {
    return (uint32_t)__cvta_generic_to_shared(p);
}
__device__ __forceinline__ void ldsm4(uint32_t& r0, uint32_t& r1, uint32_t& r2, uint32_t& r3, uint32_t a) {
    asm volatile("ldmatrix.sync.aligned.m8n8.x4.shared.b16 {%0,%1,%2,%3},[%4];"
                 : "=r"(r0), "=r"(r1), "=r"(r2), "=r"(r3) : "r"(a));
}
__device__ __forceinline__ void ldsm4t(uint32_t& r0, uint32_t& r1, uint32_t& r2, uint32_t& r3, uint32_t a) {
    asm volatile("ldmatrix.sync.aligned.m8n8.x4.trans.shared.b16 {%0,%1,%2,%3},[%4];"
                 : "=r"(r0), "=r"(r1), "=r"(r2), "=r"(r3) : "r"(a));
}
__device__ __forceinline__ void mma16816(float* c, uint32_t a0, uint32_t a1, uint32_t a2, uint32_t a3,
                                         uint32_t b0, uint32_t b1) {
    asm volatile("mma.sync.aligned.m16n8k16.row.col.f32.f16.f16.f32 "
                 "{%0,%1,%2,%3},{%4,%5,%6,%7},{%8,%9},{%0,%1,%2,%3};"
                 : "+f"(c[0]), "+f"(c[1]), "+f"(c[2]), "+f"(c[3])
                 : "r"(a0), "r"(a1), "r"(a2), "r"(a3), "r"(b0), "r"(b1));
}
__device__ __forceinline__ uint32_t packh2(float lo, float hi) {
    __half2 h = __floats2half2_rn(lo, hi);
    return *reinterpret_cast<uint32_t*>(&h);
}
__device__ __forceinline__ void cpa16(uint32_t dst, const void* src) {
    asm volatile("cp.async.cg.shared.global [%0], [%1], 16;" :: "r"(dst), "l"(src));
}
__device__ __forceinline__ void cpa_commit() { asm volatile("cp.async.commit_group;"); }
template<int N>
__device__ __forceinline__ void cpa_wait() { asm volatile("cp.async.wait_group %0;" :: "n"(N)); }

// ---------------------------------------------------------------------------
// fp32 -> fp16 converter for the 4 weight matrices (tiny: 128 blocks)
// ---------------------------------------------------------------------------
__global__ __launch_bounds__(256) void cvt_w(const float* __restrict__ w0,
                                             const float* __restrict__ w1,
                                             const float* __restrict__ w2,
                                             const float* __restrict__ w3,
                                             __half* __restrict__ dw) {
    int y = blockIdx.x >> 5;
    const float* s = (y == 0) ? w0 : (y == 1) ? w1 : (y == 2) ? w2 : w3;
    int i = ((blockIdx.x & 31) * 256 + threadIdx.x) * 8;
    float4 a = *(const float4*)(s + i);
    float4 c = *(const float4*)(s + i + 4);
    uint4 u;
    u.x = packh2(a.x, a.y); u.y = packh2(a.z, a.w);
    u.z = packh2(c.x, c.y); u.w = packh2(c.z, c.w);
    *(uint4*)(dw + y * DD * DD + i) = u;
}

// ---------------------------------------------------------------------------
// QKV GEMM, persistent over z (round-14 proven, UNCHANGED)
// ---------------------------------------------------------------------------
#define GLDH 72
#define QLDH 264
#define QA_B   (128 * QLDH * 2)
#define QW_STG (128 * GLDH * 2)
#define QKV_SMEM (QA_B + 2 * QW_STG)

__global__ __launch_bounds__(256) void qkv_k(const float* __restrict__ X,
                                             const __half* Wq, const __half* Wk, const __half* Wv,
                                             const float* bq, const float* bk, const float* bv,
                                             __half* Cq, __half* Ck, __half* Cvv) {
    extern __shared__ __align__(16) char smraw[];
    const uint32_t sA = smem_u32(smraw);
    const uint32_t sW = sA + QA_B;
    __half* sAh = (__half*)smraw;
    const int tid  = threadIdx.x;
    const int warp = tid >> 5, lane = tid & 31;
    const int wm = warp & 3, wn = warp >> 2;
    const int m0 = blockIdx.y * 128;
    const int n0 = blockIdx.x * 128;

    for (int i = tid; i < 4096; i += 256) {
        int r = i >> 5, c8 = (i & 31) * 8;
        const float* xp = X + (size_t)(m0 + r) * 256 + c8;
        float4 f0 = *(const float4*)xp, f1 = *(const float4*)(xp + 4);
        uint4 u;
        u.x = packh2(f0.x, f0.y); u.y = packh2(f0.z, f0.w);
        u.z = packh2(f1.x, f1.y); u.w = packh2(f1.z, f1.w);
        *(uint4*)(sAh + r * QLDH + c8) = u;
    }

    const uint32_t aBase = sA + ((wm * 32 + (lane & 15)) * QLDH + (lane >> 4) * 8) * 2;
    const uint32_t wBase = sW + ((wn * 64 + (lane & 7) + ((lane >> 4) & 1) * 8) * GLDH + ((lane >> 3) & 1) * 8) * 2;
    const int g = lane >> 2, qd = lane & 3;

    #pragma unroll 1
    for (int z = 0; z < 3; z++) {
        const __half* W   = (z == 0) ? Wq : (z == 1) ? Wk : Wv;
        const float* bias = (z == 0) ? bq : (z == 1) ? bk : bv;
        __half* Cv        = (z == 0) ? Cq : (z == 1) ? Ck : Cvv;
        const float scale = (z == 0) ? 0.0625f : 1.0f;

        for (int i = tid; i < 1024; i += 256) {
            int r = i >> 3, c8 = (i & 7) * 8;
            cpa16(sW + (r * GLDH + c8) * 2, W + (size_t)(n0 + r) * 256 + c8);
        }
        cpa_commit();

        float acc[2][8][4] = {};
        for (int kci = 0; kci < 4; kci++) {
            if (kci < 3) {
                const uint32_t so = ((kci + 1) & 1) * QW_STG;
                const int kc = (kci + 1) * 64;
                for (int i = tid; i < 1024; i += 256) {
                    int r = i >> 3, c8 = (i & 7) * 8;
                    cpa16(sW + so + (r * GLDH + c8) * 2, W + (size_t)(n0 + r) * 256 + kc + c8);
                }
            }
            cpa_commit();
            cpa_wait<1>();
            __syncthreads();

            const uint32_t wAddr = wBase + (kci & 1) * QW_STG;
            const uint32_t aAddr = aBase + kci * 64 * 2;
            #pragma unroll
            for (int kk = 0; kk < 4; kk++) {
                uint32_t a[2][4];
                ldsm4(a[0][0], a[0][1], a[0][2], a[0][3], aAddr + kk * 32);
                ldsm4(a[1][0], a[1][1], a[1][2], a[1][3], aAddr + 16 * QLDH * 2 + kk * 32);
                #pragma unroll
                for (int j = 0; j < 4; j++) {
                    uint32_t b0r, b1r, b2r, b3r;
                    ldsm4(b0r, b1r, b2r, b3r, wAddr + j * 16 * GLDH * 2 + kk * 32);
                    mma16816(acc[0][2 * j],     a[0][0], a[0][1], a[0][2], a[0][3], b0r, b1r);
                    mma16816(acc[0][2 * j + 1], a[0][0], a[0][1], a[0][2], a[0][3], b2r, b3r);
                    mma16816(acc[1][2 * j],     a[1][0], a[1][1], a[1][2], a[1][3], b0r, b1r);
                    mma16816(acc[1][2 * j + 1], a[1][0], a[1][1], a[1][2], a[1][3], b2r, b3r);
                }
            }
            __syncthreads();
        }

        #pragma unroll
        for (int s = 0; s < 2; s++) {
            int row0 = m0 + wm * 32 + s * 16 + g;
            #pragma unroll
            for (int j = 0; j < 8; j++) {
                int col = n0 + wn * 64 + j * 8 + qd * 2;
                float bb0 = bias[col], bb1 = bias[col + 1];
                float v00 = acc[s][j][0] + bb0, v01 = acc[s][j][1] + bb1;
                float v10 = acc[s][j][2] + bb0, v11 = acc[s][j][3] + bb1;
                *(uint32_t*)(Cv + (size_t)row0 * 256 + col)       = packh2(v00 * scale, v01 * scale);
                *(uint32_t*)(Cv + (size_t)(row0 + 8) * 256 + col) = packh2(v10 * scale, v11 * scale);
            }
        }
    }
}

// ---------------------------------------------------------------------------
// Flash attention (round-12 proven, UNCHANGED)
// ---------------------------------------------------------------------------
#define LDH 264
#define BRQ 128
#define QTILEH (BRQ * LDH)
#define TILEH (64 * LDH)
#define STGH  (2 * TILEH)
#define FLASH_SMEM ((QTILEH + 2 * STGH) * (int)sizeof(__half))
#define L2E 1.44269504f

__global__ __launch_bounds__(256, 1) void flash_h(const __half* __restrict__ Q,
                                                  const __half* __restrict__ K,
                                                  const __half* __restrict__ V,
                                                  const float* __restrict__ X,
                                                  const float* __restrict__ g1,
                                                  const float* __restrict__ be1,
                                                  __half* __restrict__ H) {
    extern __shared__ __half sm[];
    __half* sQ  = sm;
    __half* sK0 = sm + QTILEH;
    __half* sV0 = sK0 + TILEH;

    const int b  = blockIdx.y;
    const int q0 = blockIdx.x * BRQ;
    const int tid = threadIdx.x;
    const int warp = tid >> 5;
    const int lane = tid & 31;
    const int g  = lane >> 2;
    const int qd = lane & 3;

    const __half* Qb = Q + ((size_t)b * SS + q0) * DD;
    const __half* Kb = K + (size_t)b * SS * DD;
    const __half* Vb = V + (size_t)b * SS * DD;

    for (int c = tid; c < 4096; c += 256) {
        int r = c >> 5, co = (c & 31) * 8;
        cpa16(smem_u32(sQ + r * LDH + co), Qb + (size_t)r * 256 + co);
    }
    {
        const uint32_t kDst = smem_u32(sK0);
        for (int c = tid; c < 2048; c += 256) {
            int r = c >> 5, co = (c & 31) * 8;
            cpa16(kDst + (r * LDH + co) * 2,         Kb + (size_t)r * 256 + co);
            cpa16(kDst + (TILEH + r * LDH + co) * 2, Vb + (size_t)r * 256 + co);
        }
        cpa_commit();
    }

    float o[32][4];
    #pragma unroll
    for (int t = 0; t < 32; t++) { o[t][0] = 0; o[t][1] = 0; o[t][2] = 0; o[t][3] = 0; }
    float m0 = -1e30f, m1 = -1e30f, l0 = 0.0f, l1 = 0.0f;

    const uint32_t aBase  = smem_u32(sQ + (warp * 16 + (lane & 15)) * LDH + (lane >> 4) * 8);
    const uint32_t kBase0 = smem_u32(sK0 + ((lane & 7) + ((lane >> 4) & 1) * 8) * LDH + ((lane >> 3) & 1) * 8);
    const uint32_t vBase0 = smem_u32(sV0 + (lane & 15) * LDH + (lane >> 4) * 8);
    const uint32_t kDst0  = smem_u32(sK0);

    for (int ti = 0; ti < SS / 64; ti++) {
        if (ti + 1 < SS / 64) {
            const uint32_t kDst = kDst0 + ((ti + 1) & 1) * STGH * 2;
            const __half* Kn = Kb + (size_t)(ti + 1) * 64 * 256;
            const __half* Vn = Vb + (size_t)(ti + 1) * 64 * 256;
            for (int c = tid; c < 2048; c += 256) {
                int r = c >> 5, co = (c & 31) * 8;
                cpa16(kDst + (r * LDH + co) * 2,         Kn + (size_t)r * 256 + co);
                cpa16(kDst + (TILEH + r * LDH + co) * 2, Vn + (size_t)r * 256 + co);
            }
        }
        cpa_commit();
        cpa_wait<1>();
        __syncthreads();

        const uint32_t kBase = kBase0 + (ti & 1) * STGH * 2;
        const uint32_t vBase = vBase0 + (ti & 1) * STGH * 2;

        float s[8][4];
        #pragma unroll
        for (int j = 0; j < 8; j++) { s[j][0] = 0; s[j][1] = 0; s[j][2] = 0; s[j][3] = 0; }

        #pragma unroll
        for (int kk = 0; kk < 16; kk++) {
            uint32_t a0, a1, a2, a3;
            ldsm4(a0, a1, a2, a3, aBase + kk * 32);
            #pragma unroll
            for (int jj = 0; jj < 4; jj++) {
                uint32_t k0, k1, k2, k3;
                ldsm4(k0, k1, k2, k3, kBase + jj * 16 * LDH * 2 + kk * 32);
                mma16816(s[2 * jj],     a0, a1, a2, a3, k0, k1);
                mma16816(s[2 * jj + 1], a0, a1, a2, a3, k2, k3);
            }
        }

        float rmax0 = -1e30f, rmax1 = -1e30f;
        #pragma unroll
        for (int j = 0; j < 8; j++) {
            rmax0 = fmaxf(rmax0, fmaxf(s[j][0], s[j][1]));
            rmax1 = fmaxf(rmax1, fmaxf(s[j][2], s[j][3]));
        }
        rmax0 = fmaxf(rmax0, __shfl_xor_sync(0xffffffffu, rmax0, 1));
        rmax0 = fmaxf(rmax0, __shfl_xor_sync(0xffffffffu, rmax0, 2));
        rmax1 = fmaxf(rmax1, __shfl_xor_sync(0xffffffffu, rmax1, 1));
        rmax1 = fmaxf(rmax1, __shfl_xor_sync(0xffffffffu, rmax1, 2));

        float mn0 = fmaxf(m0, rmax0), mn1 = fmaxf(m1, rmax1);
        float corr0 = exp2f((m0 - mn0) * L2E);
        float corr1 = exp2f((m1 - mn1) * L2E);
        m0 = mn0; m1 = mn1;

        uint32_t pl[8], ph[8];
        float rs0 = 0.0f, rs1 = 0.0f;
        #pragma unroll
        for (int j = 0; j < 8; j++) {
            float p0 = exp2f((s[j][0] - mn0) * L2E);
            float p1 = exp2f((s[j][1] - mn0) * L2E);
            float p2 = exp2f((s[j][2] - mn1) * L2E);
            float p3 = exp2f((s[j][3] - mn1) * L2E);
            rs0 += p0 + p1; rs1 += p2 + p3;
            pl[j] = packh2(p0, p1);
            ph[j] = packh2(p2, p3);
        }
        rs0 += __shfl_xor_sync(0xffffffffu, rs0, 1);
        rs0 += __shfl_xor_sync(0xffffffffu, rs0, 2);
        rs1 += __shfl_xor_sync(0xffffffffu, rs1, 1);
        rs1 += __shfl_xor_sync(0xffffffffu, rs1, 2);
        l0 = l0 * corr0 + rs0;
        l1 = l1 * corr1 + rs1;

        #pragma unroll
        for (int t = 0; t < 32; t++) {
            o[t][0] *= corr0; o[t][1] *= corr0;
            o[t][2] *= corr1; o[t][3] *= corr1;
        }

        #pragma unroll
        for (int kk2 = 0; kk2 < 4; kk2++) {
            uint32_t a0 = pl[2 * kk2], a1 = ph[2 * kk2];
            uint32_t a2 = pl[2 * kk2 + 1], a3 = ph[2 * kk2 + 1];
            uint32_t vrow = vBase + kk2 * 16 * LDH * 2;
            #pragma unroll
            for (int nj = 0; nj < 16; nj++) {
                uint32_t v0, v1, v2, v3;
                ldsm4t(v0, v1, v2, v3, vrow + nj * 32);
                mma16816(o[2 * nj],     a0, a1, a2, a3, v0, v1);
                mma16816(o[2 * nj + 1], a0, a1, a2, a3, v2, v3);
            }
        }
        __syncthreads();
    }

    // ---- fused LN1 epilogue ----
    float inv0 = 1.0f / l0, inv1 = 1.0f / l1;
    const size_t grow0 = (size_t)(b * SS + q0 + warp * 16 + g);
    const float* x0 = X + grow0 * 256;
    const float* x1 = x0 + 8 * 256;

    float s0 = 0.0f, ss0 = 0.0f, s1 = 0.0f, ss1 = 0.0f;
    #pragma unroll
    for (int j = 0; j < 32; j++) {
        int col = j * 8 + qd * 2;
        float2 xa = *(const float2*)(x0 + col);
        float2 xb = *(const float2*)(x1 + col);
        float va0 = xa.x + o[j][0] * inv0, va1 = xa.y + o[j][1] * inv0;
        float vb0 = xb.x + o[j][2] * inv1, vb1 = xb.y + o[j][3] * inv1;
        o[j][0] = va0; o[j][1] = va1; o[j][2] = vb0; o[j][3] = vb1;
        s0 += va0 + va1; ss0 += va0 * va0 + va1 * va1;
        s1 += vb0 + vb1; ss1 += vb0 * vb0 + vb1 * vb1;
    }
    s0  += __shfl_xor_sync(0xffffffffu, s0, 1);  s0  += __shfl_xor_sync(0xffffffffu, s0, 2);
    ss0 += __shfl_xor_sync(0xffffffffu, ss0, 1); ss0 += __shfl_xor_sync(0xffffffffu, ss0, 2);
    s1  += __shfl_xor_sync(0xffffffffu, s1, 1);  s1  += __shfl_xor_sync(0xffffffffu, s1, 2);
    ss1 += __shfl_xor_sync(0xffffffffu, ss1, 1); ss1 += __shfl_xor_sync(0xffffffffu, ss1, 2);
    float mu0 = s0 * (1.0f / 256.0f), mu1 = s1 * (1.0f / 256.0f);
    float rstd0 = rsqrtf(fmaxf(ss0 * (1.0f / 256.0f) - mu0 * mu0, 0.0f) + 1e-5f);
    float rstd1 = rsqrtf(fmaxf(ss1 * (1.0f / 256.0f) - mu1 * mu1, 0.0f) + 1e-5f);

    __half* h0 = H + grow0 * 256;
    __half* h1 = h0 + 8 * 256;
    #pragma unroll
    for (int j = 0; j < 32; j++) {
        int col = j * 8 + qd * 2;
        float2 gg = *(const float2*)(g1 + col);
        float2 bb = *(const float2*)(be1 + col);
        *(uint32_t*)(h0 + col) = packh2((o[j][0] - mu0) * rstd0 * gg.x + bb.x,
                                        (o[j][1] - mu0) * rstd0 * gg.y + bb.y);
        *(uint32_t*)(h1 + col) = packh2((o[j][2] - mu1) * rstd1 * gg.x + bb.x,
                                        (o[j][3] - mu1) * rstd1 * gg.y + bb.y);
    }
}

// ---------------------------------------------------------------------------
// Fused MLP + LN2, persistent over 2 row-tiles. Round 15: warp tile m32 x n64
// (hgemm-style acc[2][8][4]) cuts ldsm traffic 33%; next h tile prefetched
// into sH during GEMM2 (sH dead after GEMM1).
// ---------------------------------------------------------------------------
#define MLDH 264
#define MWB (256 * MLDH * 2)
#define MHB (64 * MLDH * 2)
#define MLP_SMEM (MWB + 2 * MHB + 2048)

__global__ __launch_bounds__(256, 1) void mlp_k(const __half* __restrict__ H,
                                                const __half* __restrict__ Wl,
                                                const float* __restrict__ bl,
                                                const float* __restrict__ X,
                                                const float* __restrict__ g2,
                                                const float* __restrict__ be2,
                                                float* __restrict__ out) {
    extern __shared__ __align__(16) char smraw[];
    const uint32_t sW = smem_u32(smraw);
    const uint32_t sH = sW + MWB;
    const uint32_t sT = sH + MHB;
    float2* pLN = (float2*)(smraw + MWB + 2 * MHB);   // [row*4 + wn] = (sum, sumsq)

    const int tid  = threadIdx.x;
    const int warp = tid >> 5, lane = tid & 31;
    const int wm = warp & 1, wn = warp >> 1;          // m32 strips (2), n64 (4)
    const int g  = lane >> 2, qd = lane & 3;

    // ---- Wl (256x256) once + tile 0 h ----
    for (int i = tid; i < 8192; i += 256) {
        int r = i >> 5, c8 = (i & 31) * 8;
        cpa16(sW + (r * MLDH + c8) * 2, Wl + (size_t)r * 256 + c8);
    }
    cpa_commit();
    {
        const int m00 = blockIdx.x * 2 * 64;
        for (int i = tid; i < 2048; i += 256) {
            int r = i >> 5, c8 = (i & 31) * 8;
            cpa16(sH + (r * MLDH + c8) * 2, H + (size_t)(m00 + r) * 256 + c8);
        }
        cpa_commit();
    }

    const uint32_t aH = sH + (((wm * 32 + (lane & 15)) * MLDH + (lane >> 4) * 8)) * 2;
    const uint32_t aT = sT + (((wm * 32 + (lane & 15)) * MLDH + (lane >> 4) * 8)) * 2;
    const uint32_t wA = sW + (((wn * 64 + (lane & 7) + ((lane >> 4) & 1) * 8) * MLDH + ((lane >> 3) & 1) * 8)) * 2;
    const int row0 = wm * 32 + g;                     // rows row0, +8 (s=0); +16, +24 (s=1)

    for (int it = 0; it < 2; it++) {
        const int m0 = (blockIdx.x * 2 + it) * 64;

        cpa_wait<0>();
        __syncthreads();

        // ---- GEMM1: t = relu(h @ Wl^T + bl) ----
        {
            float acc[2][8][4] = {};
            #pragma unroll
            for (int kk = 0; kk < 16; kk++) {
                uint32_t a[2][4];
                ldsm4(a[0][0], a[0][1], a[0][2], a[0][3], aH + kk * 32);
                ldsm4(a[1][0], a[1][1], a[1][2], a[1][3], aH + 16 * MLDH * 2 + kk * 32);
                #pragma unroll
                for (int j = 0; j < 4; j++) {
                    uint32_t b0r, b1r, b2r, b3r;
                    ldsm4(b0r, b1r, b2r, b3r, wA + j * 16 * MLDH * 2 + kk * 32);
                    mma16816(acc[0][2 * j],     a[0][0], a[0][1], a[0][2], a[0][3], b0r, b1r);
                    mma16816(acc[0][2 * j + 1], a[0][0], a[0][1], a[0][2], a[0][3], b2r, b3r);
                    mma16816(acc[1][2 * j],     a[1][0], a[1][1], a[1][2], a[1][3], b0r, b1r);
                    mma16816(acc[1][2 * j + 1], a[1][0], a[1][1], a[1][2], a[1][3], b2r, b3r);
                }
            }
            #pragma unroll
            for (int s = 0; s < 2; s++) {
                int r = row0 + s * 16;
                #pragma unroll
                for (int j = 0; j < 8; j++) {
                    int col = wn * 64 + j * 8 + qd * 2;
                    float b0 = bl[col], b1 = bl[col + 1];
                    float v00 = fmaxf(acc[s][j][0] + b0, 0.0f), v01 = fmaxf(acc[s][j][1] + b1, 0.0f);
                    float v10 = fmaxf(acc[s][j][2] + b0, 0.0f), v11 = fmaxf(acc[s][j][3] + b1, 0.0f);
                    asm volatile("st.shared.b32 [%0], %1;" :: "r"(sT + (r * MLDH + col) * 2), "r"(packh2(v00, v01)) : "memory");
                    asm volatile("st.shared.b32 [%0], %1;" :: "r"(sT + ((r + 8) * MLDH + col) * 2), "r"(packh2(v10, v11)) : "memory");
                }
            }
        }
        __syncthreads();

        // ---- prefetch next h tile into sH (sH dead during GEMM2/LN) ----
        if (it == 0) {
            const int m1n = (blockIdx.x * 2 + 1) * 64;
            for (int i = tid; i < 2048; i += 256) {
                int r = i >> 5, c8 = (i & 31) * 8;
                cpa16(sH + (r * MLDH + c8) * 2, H + (size_t)(m1n + r) * 256 + c8);
            }
            cpa_commit();
        }

        // ---- GEMM2: t2 = t @ Wl^T + bl ----
        float acc[2][8][4] = {};
        #pragma unroll
        for (int kk = 0; kk < 16; kk++) {
            uint32_t a[2][4];
            ldsm4(a[0][0], a[0][1], a[0][2], a[0][3], aT + kk * 32);
            ldsm4(a[1][0], a[1][1], a[1][2], a[1][3], aT + 16 * MLDH * 2 + kk * 32);
            #pragma unroll
            for (int j = 0; j < 4; j++) {
                uint32_t b0r, b1r, b2r, b3r;
                ldsm4(b0r, b1r, b2r, b3r, wA + j * 16 * MLDH * 2 + kk * 32);
                mma16816(acc[0][2 * j],     a[0][0], a[0][1], a[0][2], a[0][3], b0r, b1r);
                mma16816(acc[0][2 * j + 1], a[0][0], a[0][1], a[0][2], a[0][3], b2r, b3r);
                mma16816(acc[1][2 * j],     a[1][0], a[1][1], a[1][2], a[1][3], b0r, b1r);
                mma16816(acc[1][2 * j + 1], a[1][0], a[1][1], a[1][2], a[1][3], b2r, b3r);
            }
        }
        #pragma unroll
        for (int s = 0; s < 2; s++)
            #pragma unroll
            for (int j = 0; j < 8; j++) {
                int col = wn * 64 + j * 8 + qd * 2;
                acc[s][j][0] += bl[col]; acc[s][j][1] += bl[col + 1];
                acc[s][j][2] += bl[col]; acc[s][j][3] += bl[col + 1];
            }

        // ---- fused LN2 (x folded into acc) ----
        float sm_[2][2] = {}, ssq[2][2] = {};
        #pragma unroll
        for (int s = 0; s < 2; s++) {
            const float* xa = X + (size_t)(m0 + row0 + s * 16) * 256;
            const float* xb = xa + 8 * 256;
            #pragma unroll
            for (int j = 0; j < 8; j++) {
                int col = wn * 64 + j * 8 + qd * 2;
                float2 fa = *(const float2*)(xa + col);
                float2 fb = *(const float2*)(xb + col);
                float va0 = fa.x + acc[s][j][0], va1 = fa.y + acc[s][j][1];
                float vb0 = fb.x + acc[s][j][2], vb1 = fb.y + acc[s][j][3];
                acc[s][j][0] = va0; acc[s][j][1] = va1; acc[s][j][2] = vb0; acc[s][j][3] = vb1;
                sm_[s][0] += va0 + va1; ssq[s][0] += va0 * va0 + va1 * va1;
                sm_[s][1] += vb0 + vb1; ssq[s][1] += vb0 * vb0 + vb1 * vb1;
            }
        }
        #pragma unroll
        for (int s = 0; s < 2; s++)
            #pragma unroll
            for (int hh = 0; hh < 2; hh++) {
                sm_[s][hh] += __shfl_xor_sync(0xffffffffu, sm_[s][hh], 1);
                sm_[s][hh] += __shfl_xor_sync(0xffffffffu, sm_[s][hh], 2);
                ssq[s][hh] += __shfl_xor_sync(0xffffffffu, ssq[s][hh], 1);
                ssq[s][hh] += __shfl_xor_sync(0xffffffffu, ssq[s][hh], 2);
            }
        if (qd == 0) {
            #pragma unroll
            for (int s = 0; s < 2; s++) {
                pLN[(row0 + s * 16) * 4 + wn]     = make_float2(sm_[s][0], ssq[s][0]);
                pLN[(row0 + s * 16 + 8) * 4 + wn] = make_float2(sm_[s][1], ssq[s][1]);
            }
        }
        __syncthreads();

        #pragma unroll
        for (int s = 0; s < 2; s++) {
            #pragma unroll
            for (int hh = 0; hh < 2; hh++) {
                int r = row0 + s * 16 + hh * 8;
                float2 p0 = pLN[r * 4], p1 = pLN[r * 4 + 1], p2 = pLN[r * 4 + 2], p3 = pLN[r * 4 + 3];
                float mu = (p0.x + p1.x + p2.x + p3.x) * (1.0f / 256.0f);
                float vr = (p0.y + p1.y + p2.y + p3.y) * (1.0f / 256.0f) - mu * mu;
                float rstd = rsqrtf(fmaxf(vr, 0.0f) + 1e-5f);
                float* orow = out + (size_t)(m0 + r) * 256;
                #pragma unroll
                for (int j = 0; j < 8; j++) {
                    int col = wn * 64 + j * 8 + qd * 2;
                    float2 gg = *(const float2*)(g2 + col);
                    float2 bb = *(const float2*)(be2 + col);
                    float2 w;
                    w.x = (acc[s][j][2 * hh]     - mu) * rstd * gg.x + bb.x;
                    w.y = (acc[s][j][2 * hh + 1] - mu) * rstd * gg.y + bb.y;
                    *(float2*)(orow + col) = w;
                }
            }
        }
        __syncthreads();   // pLN / sT safe before next tile
    }
}

// ---------------------------------------------------------------------------
extern "C" void kernel_launch(void* const* d_in, const int* in_sizes, int n_in,
                              void* d_out, int out_size) {
    (void)in_sizes; (void)n_in; (void)out_size;
    const float* x  = (const float*)d_in[0];
    const float* Wq = (const float*)d_in[1];
    const float* bq = (const float*)d_in[2];
    const float* Wk = (const float*)d_in[3];
    const float* bk = (const float*)d_in[4];
    const float* Wv = (const float*)d_in[5];
    const float* bv = (const float*)d_in[6];
    const float* Wl = (const float*)d_in[7];
    const float* bl = (const float*)d_in[8];
    const float* g1 = (const float*)d_in[9];
    const float* be1= (const float*)d_in[10];
    const float* g2 = (const float*)d_in[11];
    const float* be2= (const float*)d_in[12];
    float* out = (float*)d_out;

    __half *gw, *gq, *gk, *gv, *ghh;
    cudaGetSymbolAddress((void**)&gw,  g_w4);
    cudaGetSymbolAddress((void**)&gq,  g_qh);
    cudaGetSymbolAddress((void**)&gk,  g_kh);
    cudaGetSymbolAddress((void**)&gv,  g_vh);
    cudaGetSymbolAddress((void**)&ghh, g_hh);

    cudaFuncSetAttribute(flash_h, cudaFuncAttributeMaxDynamicSharedMemorySize, FLASH_SMEM);
    cudaFuncSetAttribute(qkv_k,   cudaFuncAttributeMaxDynamicSharedMemorySize, QKV_SMEM);
    cudaFuncSetAttribute(mlp_k,   cudaFuncAttributeMaxDynamicSharedMemorySize, MLP_SMEM);

    const __half* wq = gw;
    const __half* wk = gw + DD * DD;
    const __half* wv = gw + 2 * DD * DD;
    const __half* wl = gw + 3 * DD * DD;

    cvt_w<<<128, 256>>>(Wq, Wk, Wv, Wl, gw);
    qkv_k<<<dim3(2, 128), 256, QKV_SMEM>>>(x, wq, wk, wv, bq, bk, bv, gq, gk, gv);
    flash_h<<<dim3(SS / BRQ, BB), 256, FLASH_SMEM>>>(gq, gk, gv, x, g1, be1, ghh);
    mlp_k<<<ROWS / 128, 256, MLP_SMEM>>>(ghh, wl, bl, x, g2, be2, out);
}